// round 7
// baseline (speedup 1.0000x reference)
#include <cuda_runtime.h>
#include <cuda_bf16.h>
#include <mma.h>
#include <math.h>

using namespace nvcuda;

// Problem constants (fixed shapes per reference)
#define HDIM  1024
#define VOCAB 32000
#define DEPTH 10

// ---------------------------------------------------------------------------
// Device scratch (no allocations allowed). Zero-initialized at module load.
//   g_h0 / g_h1 : ping-pong hidden-state buffers, up to 1024 nodes x 1024
//   g_ghl/g_ghr : per-level GRU pre-activations (<=512 parents x 3072)
// GEMM pads M up to 128; padded rows read/write only within these buffers and
// never influence valid outputs (gate kernel only consumes i < M).
// ---------------------------------------------------------------------------
__device__ float g_h0[1024 * HDIM];
__device__ float g_h1[1024 * HDIM];
__device__ float g_ghl[512 * 3 * HDIM];
__device__ float g_ghr[512 * 3 * HDIM];

// ---------------------------------------------------------------------------
// Generic C[m][n] = sum_k A[m][k] * B[n][k]   (both row-major, K = 1024)
// tf32 wmma, fp32 accumulate. BM=BN=128, BK=32, 256 threads (8 warps),
// warp grid 4(M) x 2(N), warp tile 32x64 (2x4 fragments).
// Caller guarantees:
//   - grid.x tiles of 128 rows lie inside the A and C buffers (padded)
//   - N (grid.y * 128) divides the real N; K == 1024
// ---------------------------------------------------------------------------
#define BK 32
#define SPAD 8   // pad to 40 floats/row: keeps every wmma smem address 32B-aligned

__global__ __launch_bounds__(256) void gemm_tf32(
    const float* __restrict__ A,
    const float* __restrict__ B,
    float* __restrict__ C,
    int ldc)
{
    __shared__ float As[128][BK + SPAD];
    __shared__ float Bs[128][BK + SPAD];

    const int m0 = blockIdx.x * 128;
    const int n0 = blockIdx.y * 128;
    const int tid = threadIdx.x;
    const int wid = tid >> 5;
    const int wm = wid >> 1;   // 0..3  -> rows  wm*32 .. wm*32+31
    const int wn = wid & 1;    // 0..1  -> cols  wn*64 .. wn*64+63

    wmma::fragment<wmma::accumulator, 16, 16, 8, float> acc[2][4];
#pragma unroll
    for (int i = 0; i < 2; ++i)
#pragma unroll
        for (int j = 0; j < 4; ++j)
            wmma::fill_fragment(acc[i][j], 0.0f);

    for (int k0 = 0; k0 < HDIM; k0 += BK) {
        // Load 128x32 fp32 tiles of A and B. 1024 float4 each; 4 per thread.
#pragma unroll
        for (int i = 0; i < 4; ++i) {
            int lin = i * 256 + tid;        // 0..1023
            int row = lin >> 3;             // 0..127
            int c4  = lin & 7;              // 0..7 (float4 column)
            float4 va = *(const float4*)(A + (size_t)(m0 + row) * HDIM + k0 + c4 * 4);
            *(float4*)(&As[row][c4 * 4]) = va;
            float4 vb = *(const float4*)(B + (size_t)(n0 + row) * HDIM + k0 + c4 * 4);
            *(float4*)(&Bs[row][c4 * 4]) = vb;
        }
        __syncthreads();

#pragma unroll
        for (int ks = 0; ks < BK; ks += 8) {
            wmma::fragment<wmma::matrix_a, 16, 16, 8, wmma::precision::tf32, wmma::row_major> af[2];
            wmma::fragment<wmma::matrix_b, 16, 16, 8, wmma::precision::tf32, wmma::col_major> bf[4];
#pragma unroll
            for (int i = 0; i < 2; ++i) {
                wmma::load_matrix_sync(af[i], &As[wm * 32 + i * 16][ks], BK + SPAD);
#pragma unroll
                for (int t = 0; t < af[i].num_elements; ++t)
                    af[i].x[t] = wmma::__float_to_tf32(af[i].x[t]);
            }
#pragma unroll
            for (int j = 0; j < 4; ++j) {
                wmma::load_matrix_sync(bf[j], &Bs[wn * 64 + j * 16][ks], BK + SPAD);
#pragma unroll
                for (int t = 0; t < bf[j].num_elements; ++t)
                    bf[j].x[t] = wmma::__float_to_tf32(bf[j].x[t]);
            }
#pragma unroll
            for (int i = 0; i < 2; ++i)
#pragma unroll
                for (int j = 0; j < 4; ++j)
                    wmma::mma_sync(acc[i][j], af[i], bf[j], acc[i][j]);
        }
        __syncthreads();
    }

#pragma unroll
    for (int i = 0; i < 2; ++i)
#pragma unroll
        for (int j = 0; j < 4; ++j) {
            float* cp = C + (size_t)(m0 + wm * 32 + i * 16) * ldc + (n0 + wn * 64 + j * 16);
            wmma::store_matrix_sync(cp, acc[i][j], ldc, wmma::mem_row_major);
        }
}

// ---------------------------------------------------------------------------
// GRU gates for one level. ghl/ghr are raw h@W^T (NO bias). PyTorch GRU with
// zero input:
//   r = sigmoid(bih_r_gate + (gh_r_gate + bhh_r_gate))
//   z = sigmoid(bih_z      + (gh_z      + bhh_z))
//   n = tanh   (bih_n + r * (gh_n      + bhh_n))      <-- bhh_n inside r*()
//   h' = (1-z)*n + z*h
// Children interleave: child(2i)=left(i), child(2i+1)=right(i).
// ---------------------------------------------------------------------------
__device__ __forceinline__ float sigmoidf_(float x) { return 1.0f / (1.0f + expf(-x)); }

__global__ void gru_gate(
    const float* __restrict__ hprev,
    const float* __restrict__ ghl, const float* __restrict__ ghr,
    const float* __restrict__ bih_l, const float* __restrict__ bhh_l,
    const float* __restrict__ bih_r, const float* __restrict__ bhh_r,
    float* __restrict__ hnext, int M)
{
    int idx = blockIdx.x * blockDim.x + threadIdx.x;
    if (idx >= M * HDIM) return;
    int i = idx >> 10;          // parent node
    int j = idx & (HDIM - 1);   // feature

    float h = hprev[idx];

    // left child
    {
        const float* gh = ghl + (size_t)i * 3 * HDIM;
        float gr = gh[j]            + bhh_l[j];
        float gz = gh[HDIM + j]     + bhh_l[HDIM + j];
        float gn = gh[2 * HDIM + j] + bhh_l[2 * HDIM + j];
        float r = sigmoidf_(bih_l[j] + gr);
        float z = sigmoidf_(bih_l[HDIM + j] + gz);
        float n = tanhf(bih_l[2 * HDIM + j] + r * gn);
        hnext[(size_t)(2 * i) * HDIM + j] = (1.0f - z) * n + z * h;
    }
    // right child
    {
        const float* gh = ghr + (size_t)i * 3 * HDIM;
        float gr = gh[j]            + bhh_r[j];
        float gz = gh[HDIM + j]     + bhh_r[HDIM + j];
        float gn = gh[2 * HDIM + j] + bhh_r[2 * HDIM + j];
        float r = sigmoidf_(bih_r[j] + gr);
        float z = sigmoidf_(bih_r[HDIM + j] + gz);
        float n = tanhf(bih_r[2 * HDIM + j] + r * gn);
        hnext[(size_t)(2 * i + 1) * HDIM + j] = (1.0f - z) * n + z * h;
    }
}

// ---------------------------------------------------------------------------
// In-place log_softmax over rows of x (1024 x VOCAB), fusing the output bias:
//   y[j] = (x[j]+b[j]) - max - log(sum exp(x+b-max))
// One block per row, 256 threads, 125 elems/thread.
// ---------------------------------------------------------------------------
__global__ __launch_bounds__(256) void logsoftmax_bias(
    float* __restrict__ x, const float* __restrict__ b)
{
    const int row = blockIdx.x;
    float* xr = x + (size_t)row * VOCAB;
    __shared__ float red[256];
    const int tid = threadIdx.x;

    float m = -1e30f;
    for (int j = tid; j < VOCAB; j += 256) m = fmaxf(m, xr[j] + b[j]);
    red[tid] = m;
    __syncthreads();
    for (int s = 128; s > 0; s >>= 1) {
        if (tid < s) red[tid] = fmaxf(red[tid], red[tid + s]);
        __syncthreads();
    }
    m = red[0];
    __syncthreads();

    float sum = 0.0f;
    for (int j = tid; j < VOCAB; j += 256) sum += expf(xr[j] + b[j] - m);
    red[tid] = sum;
    __syncthreads();
    for (int s = 128; s > 0; s >>= 1) {
        if (tid < s) red[tid] += red[tid + s];
        __syncthreads();
    }
    float lse = m + logf(red[0]);
    __syncthreads();

    for (int j = tid; j < VOCAB; j += 256) xr[j] = xr[j] + b[j] - lse;
}

__global__ void copy_row(const float* __restrict__ src, float* __restrict__ dst)
{
    int i = blockIdx.x * 256 + threadIdx.x;
    if (i < HDIM) dst[i] = src[i];
}

// ---------------------------------------------------------------------------
// Launch: 33 kernels, all on the default stream, graph-capturable,
// allocation-free (scratch lives in __device__ globals).
// ---------------------------------------------------------------------------
extern "C" void kernel_launch(void* const* d_in, const int* in_sizes, int n_in,
                              void* d_out, int out_size)
{
    (void)in_sizes; (void)n_in; (void)out_size;

    const float* hidden = (const float*)d_in[0];
    const float* Whh_l  = (const float*)d_in[1];
    const float* bih_l  = (const float*)d_in[2];
    const float* bhh_l  = (const float*)d_in[3];
    const float* Whh_r  = (const float*)d_in[4];
    const float* bih_r  = (const float*)d_in[5];
    const float* bhh_r  = (const float*)d_in[6];
    const float* Wout   = (const float*)d_in[7];
    const float* bout   = (const float*)d_in[8];
    float* out = (float*)d_out;

    float *h0, *h1, *ghl, *ghr;
    cudaGetSymbolAddress((void**)&h0,  g_h0);
    cudaGetSymbolAddress((void**)&h1,  g_h1);
    cudaGetSymbolAddress((void**)&ghl, g_ghl);
    cudaGetSymbolAddress((void**)&ghr, g_ghr);
    float* bufs[2] = { h0, h1 };

    // Root hidden state -> g_h0 row 0
    copy_row<<<4, 256>>>(hidden, h0);

    // Tree expansion: level l has M = 2^l parents, produces 2M children.
    for (int l = 0; l < DEPTH; ++l) {
        int M = 1 << l;
        float* hin  = bufs[l & 1];
        float* hout = bufs[(l + 1) & 1];
        int mt = (M + 127) / 128;                 // padded M tiles
        dim3 grid(mt, 3 * HDIM / 128);            // 3072/128 = 24 N-tiles
        gemm_tf32<<<grid, 256>>>(hin, Whh_l, ghl, 3 * HDIM);
        gemm_tf32<<<grid, 256>>>(hin, Whh_r, ghr, 3 * HDIM);
        gru_gate<<<M * (HDIM / 256), 256>>>(hin, ghl, ghr,
                                            bih_l, bhh_l, bih_r, bhh_r,
                                            hout, M);
    }

    // Output projection: leaves (1024 x 1024) @ Wout^T -> d_out (1024 x 32000)
    // grid.x = M-tiles (fast-varying) so consecutive CTAs share the same Wout
    // N-tile -> Wout streamed from HBM once, reused via L2 across M-tiles.
    dim3 gout(1024 / 128, VOCAB / 128);           // (8, 250)
    gemm_tf32<<<gout, 256>>>(bufs[DEPTH & 1], Wout, out, VOCAB);

    // Fused +bout and in-place log_softmax
    logsoftmax_bias<<<1024, 256>>>(out, bout);
}

// round 8
// speedup vs baseline: 1.5771x; 1.5771x over previous
#include <cuda_runtime.h>
#include <cuda_bf16.h>
#include <mma.h>
#include <math.h>

using namespace nvcuda;

#define HDIM  1024
#define VOCAB 32000
#define DEPTH 10

// ---------------------------------------------------------------------------
// Device scratch (allocation-free).
// ---------------------------------------------------------------------------
__device__ float g_h0[1024 * HDIM];
__device__ float g_h1[1024 * HDIM];
__device__ float g_ghl[512 * 3 * HDIM];
__device__ float g_ghr[512 * 3 * HDIM];

// ---------------------------------------------------------------------------
// Double-buffered cp.async tf32 GEMM core.
// C[m][n] = sum_k A[m][k]*B[n][k], A,B row-major, K = HDIM = 1024.
// BM=BN=128, BK=32, 256 threads (8 warps: 4(M) x 2(N)), warp tile 32x64.
// smem: 2 stages x (A 128x36 + B 128x36) fp32 = 73728 B (dynamic).
// ---------------------------------------------------------------------------
#define SSTRIDE 36                    // 32 + 4 pad; 144B rows keep 16B align
#define STILE   (128 * SSTRIDE)      // floats per tile
#define SMEM_BYTES (2 * 2 * STILE * 4)

__device__ __forceinline__ void cpa16(float* dst, const float* src) {
    unsigned d = (unsigned)__cvta_generic_to_shared(dst);
    asm volatile("cp.async.cg.shared.global [%0], [%1], 16;\n" :: "r"(d), "l"(src));
}
__device__ __forceinline__ void cpa_commit() {
    asm volatile("cp.async.commit_group;\n" ::);
}
template <int N>
__device__ __forceinline__ void cpa_wait() {
    asm volatile("cp.async.wait_group %0;\n" :: "n"(N));
}

__device__ __forceinline__ void load_stage(
    const float* __restrict__ A, const float* __restrict__ B,
    int m0, int n0, int k0, float* As, float* Bs, int tid)
{
#pragma unroll
    for (int i = 0; i < 4; ++i) {
        int lin = i * 256 + tid;        // 0..1023
        int row = lin >> 3;             // 0..127
        int c4  = lin & 7;              // float4 column
        cpa16(As + row * SSTRIDE + c4 * 4, A + (size_t)(m0 + row) * HDIM + k0 + c4 * 4);
        cpa16(Bs + row * SSTRIDE + c4 * 4, B + (size_t)(n0 + row) * HDIM + k0 + c4 * 4);
    }
    cpa_commit();
}

__device__ __forceinline__ void gemm_core(
    const float* __restrict__ A, const float* __restrict__ B,
    float* __restrict__ C, int ldc, int m0, int n0, float* smem)
{
    const int tid = threadIdx.x;
    const int wid = tid >> 5;
    const int wm = wid >> 1;            // 0..3
    const int wn = wid & 1;             // 0..1

    wmma::fragment<wmma::accumulator, 16, 16, 8, float> acc[2][4];
#pragma unroll
    for (int i = 0; i < 2; ++i)
#pragma unroll
        for (int j = 0; j < 4; ++j)
            wmma::fill_fragment(acc[i][j], 0.0f);

    // stage s: As = smem + s*2*STILE, Bs = As + STILE
    load_stage(A, B, m0, n0, 0, smem, smem + STILE, tid);

    const int KT = HDIM / 32;           // 32
#pragma unroll 1
    for (int kt = 0; kt < KT; ++kt) {
        float* base = smem + (size_t)(kt & 1) * 2 * STILE;
        float* As = base;
        float* Bs = base + STILE;

        if (kt + 1 < KT) {
            float* nb = smem + (size_t)((kt + 1) & 1) * 2 * STILE;
            load_stage(A, B, m0, n0, (kt + 1) * 32, nb, nb + STILE, tid);
            cpa_wait<1>();
        } else {
            cpa_wait<0>();
        }
        __syncthreads();

#pragma unroll
        for (int ks = 0; ks < 32; ks += 8) {
            wmma::fragment<wmma::matrix_a, 16, 16, 8, wmma::precision::tf32, wmma::row_major> af[2];
            wmma::fragment<wmma::matrix_b, 16, 16, 8, wmma::precision::tf32, wmma::col_major> bf[4];
#pragma unroll
            for (int i = 0; i < 2; ++i) {
                wmma::load_matrix_sync(af[i], As + (wm * 32 + i * 16) * SSTRIDE + ks, SSTRIDE);
#pragma unroll
                for (int t = 0; t < af[i].num_elements; ++t)
                    af[i].x[t] = wmma::__float_to_tf32(af[i].x[t]);
            }
#pragma unroll
            for (int j = 0; j < 4; ++j) {
                wmma::load_matrix_sync(bf[j], Bs + (wn * 64 + j * 16) * SSTRIDE + ks, SSTRIDE);
#pragma unroll
                for (int t = 0; t < bf[j].num_elements; ++t)
                    bf[j].x[t] = wmma::__float_to_tf32(bf[j].x[t]);
            }
#pragma unroll
            for (int i = 0; i < 2; ++i)
#pragma unroll
                for (int j = 0; j < 4; ++j)
                    wmma::mma_sync(acc[i][j], af[i], bf[j], acc[i][j]);
        }
        __syncthreads();   // protect buffer (kt&1) before iter kt+1 overwrites it
    }

#pragma unroll
    for (int i = 0; i < 2; ++i)
#pragma unroll
        for (int j = 0; j < 4; ++j) {
            float* cp = C + (size_t)(m0 + wm * 32 + i * 16) * ldc + (n0 + wn * 64 + j * 16);
            wmma::store_matrix_sync(cp, acc[i][j], ldc, wmma::mem_row_major);
        }
}

// Fused left+right GRU pre-activation GEMM: grid (mt, 48).
__global__ __launch_bounds__(256) void gemm_gru(
    const float* __restrict__ hin,
    const float* __restrict__ Wl, const float* __restrict__ Wr,
    float* __restrict__ ghl, float* __restrict__ ghr)
{
    extern __shared__ float smem[];
    int ny = blockIdx.y;
    const float* B = (ny < 24) ? Wl : Wr;
    float* C = (ny < 24) ? ghl : ghr;
    int n0 = ((ny < 24) ? ny : ny - 24) * 128;
    gemm_core(hin, B, C, 3 * HDIM, blockIdx.x * 128, n0, smem);
}

// Output projection GEMM: grid (8, 250).
__global__ __launch_bounds__(256) void gemm_out(
    const float* __restrict__ A, const float* __restrict__ B, float* __restrict__ C)
{
    extern __shared__ float smem[];
    gemm_core(A, B, C, VOCAB, blockIdx.x * 128, blockIdx.y * 128, smem);
}

// ---------------------------------------------------------------------------
// GRU gates (PyTorch semantics, zero input; bhh_n inside r*()).
// ---------------------------------------------------------------------------
__device__ __forceinline__ float sigmoidf_(float x) { return 1.0f / (1.0f + expf(-x)); }

__global__ void gru_gate(
    const float* __restrict__ hprev,
    const float* __restrict__ ghl, const float* __restrict__ ghr,
    const float* __restrict__ bih_l, const float* __restrict__ bhh_l,
    const float* __restrict__ bih_r, const float* __restrict__ bhh_r,
    float* __restrict__ hnext, int M)
{
    int idx = blockIdx.x * blockDim.x + threadIdx.x;
    if (idx >= M * HDIM) return;
    int i = idx >> 10;
    int j = idx & (HDIM - 1);

    float h = hprev[idx];
    {
        const float* gh = ghl + (size_t)i * 3 * HDIM;
        float r = sigmoidf_(bih_l[j]            + gh[j]            + bhh_l[j]);
        float z = sigmoidf_(bih_l[HDIM + j]     + gh[HDIM + j]     + bhh_l[HDIM + j]);
        float n = tanhf(bih_l[2 * HDIM + j] + r * (gh[2 * HDIM + j] + bhh_l[2 * HDIM + j]));
        hnext[(size_t)(2 * i) * HDIM + j] = (1.0f - z) * n + z * h;
    }
    {
        const float* gh = ghr + (size_t)i * 3 * HDIM;
        float r = sigmoidf_(bih_r[j]            + gh[j]            + bhh_r[j]);
        float z = sigmoidf_(bih_r[HDIM + j]     + gh[HDIM + j]     + bhh_r[HDIM + j]);
        float n = tanhf(bih_r[2 * HDIM + j] + r * (gh[2 * HDIM + j] + bhh_r[2 * HDIM + j]));
        hnext[(size_t)(2 * i + 1) * HDIM + j] = (1.0f - z) * n + z * h;
    }
}

// ---------------------------------------------------------------------------
// Online (single-pass max+sum) log_softmax with fused bias, float4 I/O.
// One block per row (1024 rows x 32000 cols), in place.
// ---------------------------------------------------------------------------
__global__ __launch_bounds__(256) void logsoftmax_bias(
    float* __restrict__ x, const float* __restrict__ b)
{
    const int row = blockIdx.x;
    float* xr = x + (size_t)row * VOCAB;
    const float4* x4 = (const float4*)xr;
    const float4* b4 = (const float4*)b;
    __shared__ float rm[256], rs[256];
    const int tid = threadIdx.x;

    float m = -1e30f, s = 0.0f;
    for (int j = tid; j < VOCAB / 4; j += 256) {
        float4 v = x4[j], bb = b4[j];
        float t0 = v.x + bb.x, t1 = v.y + bb.y, t2 = v.z + bb.z, t3 = v.w + bb.w;
        float mn = fmaxf(fmaxf(t0, t1), fmaxf(t2, t3));
        if (mn > m) { s *= expf(m - mn); m = mn; }
        s += expf(t0 - m) + expf(t1 - m) + expf(t2 - m) + expf(t3 - m);
    }
    rm[tid] = m; rs[tid] = s;
    __syncthreads();
    for (int st = 128; st > 0; st >>= 1) {
        if (tid < st) {
            float m2 = rm[tid + st], s2 = rs[tid + st];
            float mm = fmaxf(rm[tid], m2);
            rs[tid] = rs[tid] * expf(rm[tid] - mm) + s2 * expf(m2 - mm);
            rm[tid] = mm;
        }
        __syncthreads();
    }
    float lse = rm[0] + logf(rs[0]);

    float4* xw = (float4*)xr;
    for (int j = tid; j < VOCAB / 4; j += 256) {
        float4 v = xw[j], bb = b4[j];
        v.x = v.x + bb.x - lse; v.y = v.y + bb.y - lse;
        v.z = v.z + bb.z - lse; v.w = v.w + bb.w - lse;
        xw[j] = v;
    }
}

__global__ void copy_row(const float* __restrict__ src, float* __restrict__ dst)
{
    int i = blockIdx.x * 256 + threadIdx.x;
    if (i < HDIM) dst[i] = src[i];
}

// ---------------------------------------------------------------------------
// 23 launches, graph-capturable, allocation-free.
// ---------------------------------------------------------------------------
extern "C" void kernel_launch(void* const* d_in, const int* in_sizes, int n_in,
                              void* d_out, int out_size)
{
    (void)in_sizes; (void)n_in; (void)out_size;

    const float* hidden = (const float*)d_in[0];
    const float* Whh_l  = (const float*)d_in[1];
    const float* bih_l  = (const float*)d_in[2];
    const float* bhh_l  = (const float*)d_in[3];
    const float* Whh_r  = (const float*)d_in[4];
    const float* bih_r  = (const float*)d_in[5];
    const float* bhh_r  = (const float*)d_in[6];
    const float* Wout   = (const float*)d_in[7];
    const float* bout   = (const float*)d_in[8];
    float* out = (float*)d_out;

    cudaFuncSetAttribute(gemm_gru, cudaFuncAttributeMaxDynamicSharedMemorySize, SMEM_BYTES);
    cudaFuncSetAttribute(gemm_out, cudaFuncAttributeMaxDynamicSharedMemorySize, SMEM_BYTES);

    float *h0, *h1, *ghl, *ghr;
    cudaGetSymbolAddress((void**)&h0,  g_h0);
    cudaGetSymbolAddress((void**)&h1,  g_h1);
    cudaGetSymbolAddress((void**)&ghl, g_ghl);
    cudaGetSymbolAddress((void**)&ghr, g_ghr);
    float* bufs[2] = { h0, h1 };

    copy_row<<<4, 256>>>(hidden, h0);

    for (int l = 0; l < DEPTH; ++l) {
        int M = 1 << l;
        float* hin  = bufs[l & 1];
        float* hout = bufs[(l + 1) & 1];
        int mt = (M + 127) / 128;
        dim3 grid(mt, 48);                        // 24 N-tiles x {left,right}
        gemm_gru<<<grid, 256, SMEM_BYTES>>>(hin, Whh_l, Whh_r, ghl, ghr);
        gru_gate<<<M * (HDIM / 256), 256>>>(hin, ghl, ghr,
                                            bih_l, bhh_l, bih_r, bhh_r,
                                            hout, M);
    }

    dim3 gout(1024 / 128, VOCAB / 128);           // (8, 250); x-fast -> Wout L2 reuse
    gemm_out<<<gout, 256, SMEM_BYTES>>>(bufs[DEPTH & 1], Wout, out);

    logsoftmax_bias<<<1024, 256>>>(out, bout);
}

// round 10
// speedup vs baseline: 2.1401x; 1.3570x over previous
#include <cuda_runtime.h>
#include <cuda_bf16.h>
#include <mma.h>
#include <math.h>

using namespace nvcuda;

#define HDIM  1024
#define VOCAB 32000
#define DEPTH 10

// ---------------------------------------------------------------------------
// Device scratch (allocation-free).
//   g_h0/g_h1 : ping-pong hidden states (1024 x 1024)
//   g_ghl/ghr : split-K partial pre-activations.
//               max need: level 9 -> S=4 splits x 512 rows x 3072 = 6.29M floats
// ---------------------------------------------------------------------------
__device__ float g_h0[1024 * HDIM];
__device__ float g_h1[1024 * HDIM];
__device__ float g_ghl[4 * 512 * 3 * HDIM];
__device__ float g_ghr[4 * 512 * 3 * HDIM];

// ---------------------------------------------------------------------------
// tf32 wmma GEMM core, templated tile config, 2-stage cp.async double buffer.
// C[m][n] = sum_{k in [kb,ke)} A[m][k]*B[n][k]; A,B row-major, lda=ldb=HDIM.
// Warps arranged WR x WC; each warp computes (MI*16) x (NI*16).
// ---------------------------------------------------------------------------
#define SSTRIDE 36                    // 32 + 4 pad (144B rows, 16B aligned)

__device__ __forceinline__ void cpa16(float* dst, const float* src) {
    unsigned d = (unsigned)__cvta_generic_to_shared(dst);
    asm volatile("cp.async.cg.shared.global [%0], [%1], 16;\n" :: "r"(d), "l"(src));
}
__device__ __forceinline__ void cpa_commit() {
    asm volatile("cp.async.commit_group;\n" ::);
}
template <int N>
__device__ __forceinline__ void cpa_wait() {
    asm volatile("cp.async.wait_group %0;\n" :: "n"(N));
}

template<int BM, int BN, int NT>
__device__ __forceinline__ void load_stage(
    const float* __restrict__ A, const float* __restrict__ B,
    int m0, int n0, int k0, float* s, int tid)
{
    float* As = s;
    float* Bs = s + BM * SSTRIDE;
    constexpr int TOT = (BM + BN) * 8;     // float4 transfers per stage (BK=32)
#pragma unroll
    for (int i = 0; i < TOT / NT; ++i) {
        int lin = i * NT + tid;
        int row = lin >> 3;
        int c4  = lin & 7;
        if (row < BM)
            cpa16(As + row * SSTRIDE + c4 * 4,
                  A + (size_t)(m0 + row) * HDIM + k0 + c4 * 4);
        else
            cpa16(Bs + (row - BM) * SSTRIDE + c4 * 4,
                  B + (size_t)(n0 + row - BM) * HDIM + k0 + c4 * 4);
    }
    cpa_commit();
}

template<int BM, int BN, int WR, int WC, int MI, int NI>
__device__ __forceinline__ void gemm_core(
    const float* __restrict__ A, const float* __restrict__ B,
    float* __restrict__ C, int ldc, int m0, int n0, int kb, int ke, float* smem)
{
    constexpr int NT = WR * WC * 32;
    constexpr int STAGE = (BM + BN) * SSTRIDE;
    const int tid = threadIdx.x;
    const int wid = tid >> 5;
    const int wm = wid % WR;
    const int wn = wid / WR;

    wmma::fragment<wmma::accumulator, 16, 16, 8, float> acc[MI][NI];
#pragma unroll
    for (int i = 0; i < MI; ++i)
#pragma unroll
        for (int j = 0; j < NI; ++j)
            wmma::fill_fragment(acc[i][j], 0.0f);

    load_stage<BM, BN, NT>(A, B, m0, n0, kb, smem, tid);

    const int nk = (ke - kb) >> 5;
#pragma unroll 1
    for (int kt = 0; kt < nk; ++kt) {
        float* s = smem + (size_t)(kt & 1) * STAGE;
        if (kt + 1 < nk) {
            load_stage<BM, BN, NT>(A, B, m0, n0, kb + ((kt + 1) << 5),
                                   smem + (size_t)((kt + 1) & 1) * STAGE, tid);
            cpa_wait<1>();
        } else {
            cpa_wait<0>();
        }
        __syncthreads();

        float* As = s;
        float* Bs = s + BM * SSTRIDE;
#pragma unroll
        for (int ks = 0; ks < 32; ks += 8) {
            wmma::fragment<wmma::matrix_a, 16, 16, 8, wmma::precision::tf32, wmma::row_major> af[MI];
            wmma::fragment<wmma::matrix_b, 16, 16, 8, wmma::precision::tf32, wmma::col_major> bf[NI];
#pragma unroll
            for (int i = 0; i < MI; ++i)
                wmma::load_matrix_sync(af[i], As + (wm * MI * 16 + i * 16) * SSTRIDE + ks, SSTRIDE);
#pragma unroll
            for (int j = 0; j < NI; ++j)
                wmma::load_matrix_sync(bf[j], Bs + (wn * NI * 16 + j * 16) * SSTRIDE + ks, SSTRIDE);
#pragma unroll
            for (int i = 0; i < MI; ++i)
#pragma unroll
                for (int j = 0; j < NI; ++j)
                    wmma::mma_sync(acc[i][j], af[i], bf[j], acc[i][j]);
        }
        __syncthreads();
    }

#pragma unroll
    for (int i = 0; i < MI; ++i)
#pragma unroll
        for (int j = 0; j < NI; ++j) {
            float* cp = C + (size_t)(m0 + wm * MI * 16 + i * 16) * ldc
                          + (n0 + wn * NI * 16 + j * 16);
            wmma::store_matrix_sync(cp, acc[i][j], ldc, wmma::mem_row_major);
        }
}

// ---------------------------------------------------------------------------
// Split-K fused left+right GRU pre-activation GEMM.
// grid (mt, 48, S): y<24 -> left W/out, y>=24 -> right; z = K split.
// Partial z is written at C + z*pstride (summed later by gru_gate).
// ---------------------------------------------------------------------------
#define SMEM_GRU ((128 + 128) * SSTRIDE * 2 * 4)
#define SMEM_OUT ((128 + 256) * SSTRIDE * 2 * 4)

__global__ __launch_bounds__(256) void gemm_gru(
    const float* __restrict__ hin,
    const float* __restrict__ Wl, const float* __restrict__ Wr,
    float* __restrict__ ghl, float* __restrict__ ghr,
    int kchunk, int pstride)
{
    extern __shared__ float smem[];
    int ny = blockIdx.y;
    const float* B = (ny < 24) ? Wl : Wr;
    float* Cb = (ny < 24) ? ghl : ghr;
    int n0 = ((ny < 24) ? ny : ny - 24) * 128;
    float* C = Cb + (size_t)blockIdx.z * pstride;
    int kb = blockIdx.z * kchunk;
    gemm_core<128, 128, 4, 2, 2, 4>(hin, B, C, 3 * HDIM,
                                    blockIdx.x * 128, n0, kb, kb + kchunk, smem);
}

// Output projection: block tile 128x256, warp tile 64x64. grid (8, 125).
__global__ __launch_bounds__(256) void gemm_out(
    const float* __restrict__ A, const float* __restrict__ B, float* __restrict__ C)
{
    extern __shared__ float smem[];
    gemm_core<128, 256, 2, 4, 4, 4>(A, B, C, VOCAB,
                                    blockIdx.x * 128, blockIdx.y * 256, 0, HDIM, smem);
}

// ---------------------------------------------------------------------------
// GRU gates with split-K partial summation (PyTorch semantics, zero input).
// ---------------------------------------------------------------------------
__device__ __forceinline__ float sigmoidf_(float x) { return 1.0f / (1.0f + expf(-x)); }

__global__ void gru_gate(
    const float* __restrict__ hprev,
    const float* __restrict__ ghl, const float* __restrict__ ghr,
    const float* __restrict__ bih_l, const float* __restrict__ bhh_l,
    const float* __restrict__ bih_r, const float* __restrict__ bhh_r,
    float* __restrict__ hnext, int M, int S, int pstride)
{
    int idx = blockIdx.x * blockDim.x + threadIdx.x;
    if (idx >= M * HDIM) return;
    int i = idx >> 10;
    int j = idx & (HDIM - 1);

    float h = hprev[idx];
    {
        float gr = 0.f, gz = 0.f, gn = 0.f;
        for (int s = 0; s < S; ++s) {
            const float* gh = ghl + (size_t)s * pstride + (size_t)i * 3 * HDIM;
            gr += gh[j]; gz += gh[HDIM + j]; gn += gh[2 * HDIM + j];
        }
        float r = sigmoidf_(bih_l[j]        + gr + bhh_l[j]);
        float z = sigmoidf_(bih_l[HDIM + j] + gz + bhh_l[HDIM + j]);
        float n = tanhf(bih_l[2 * HDIM + j] + r * (gn + bhh_l[2 * HDIM + j]));
        hnext[(size_t)(2 * i) * HDIM + j] = (1.0f - z) * n + z * h;
    }
    {
        float gr = 0.f, gz = 0.f, gn = 0.f;
        for (int s = 0; s < S; ++s) {
            const float* gh = ghr + (size_t)s * pstride + (size_t)i * 3 * HDIM;
            gr += gh[j]; gz += gh[HDIM + j]; gn += gh[2 * HDIM + j];
        }
        float r = sigmoidf_(bih_r[j]        + gr + bhh_r[j]);
        float z = sigmoidf_(bih_r[HDIM + j] + gz + bhh_r[HDIM + j]);
        float n = tanhf(bih_r[2 * HDIM + j] + r * (gn + bhh_r[2 * HDIM + j]));
        hnext[(size_t)(2 * i + 1) * HDIM + j] = (1.0f - z) * n + z * h;
    }
}

// ---------------------------------------------------------------------------
// Online single-pass log_softmax with fused bias, float4 I/O, in place.
// ---------------------------------------------------------------------------
__global__ __launch_bounds__(256) void logsoftmax_bias(
    float* __restrict__ x, const float* __restrict__ b)
{
    const int row = blockIdx.x;
    float* xr = x + (size_t)row * VOCAB;
    const float4* x4 = (const float4*)xr;
    const float4* b4 = (const float4*)b;
    __shared__ float rm[256], rs[256];
    const int tid = threadIdx.x;

    float m = -1e30f, s = 0.0f;
    for (int j = tid; j < VOCAB / 4; j += 256) {
        float4 v = x4[j], bb = b4[j];
        float t0 = v.x + bb.x, t1 = v.y + bb.y, t2 = v.z + bb.z, t3 = v.w + bb.w;
        float mn = fmaxf(fmaxf(t0, t1), fmaxf(t2, t3));
        if (mn > m) { s *= expf(m - mn); m = mn; }
        s += expf(t0 - m) + expf(t1 - m) + expf(t2 - m) + expf(t3 - m);
    }
    rm[tid] = m; rs[tid] = s;
    __syncthreads();
    for (int st = 128; st > 0; st >>= 1) {
        if (tid < st) {
            float m2 = rm[tid + st], s2 = rs[tid + st];
            float mm = fmaxf(rm[tid], m2);
            rs[tid] = rs[tid] * expf(rm[tid] - mm) + s2 * expf(m2 - mm);
            rm[tid] = mm;
        }
        __syncthreads();
    }
    float lse = rm[0] + logf(rs[0]);

    float4* xw = (float4*)xr;
    for (int j = tid; j < VOCAB / 4; j += 256) {
        float4 v = xw[j], bb = b4[j];
        v.x = v.x + bb.x - lse; v.y = v.y + bb.y - lse;
        v.z = v.z + bb.z - lse; v.w = v.w + bb.w - lse;
        xw[j] = v;
    }
}

__global__ void copy_row(const float* __restrict__ src, float* __restrict__ dst)
{
    int i = blockIdx.x * 256 + threadIdx.x;
    if (i < HDIM) dst[i] = src[i];
}

// ---------------------------------------------------------------------------
// 23 launches, graph-capturable, allocation-free.
// ---------------------------------------------------------------------------
extern "C" void kernel_launch(void* const* d_in, const int* in_sizes, int n_in,
                              void* d_out, int out_size)
{
    (void)in_sizes; (void)n_in; (void)out_size;

    const float* hidden = (const float*)d_in[0];
    const float* Whh_l  = (const float*)d_in[1];
    const float* bih_l  = (const float*)d_in[2];
    const float* bhh_l  = (const float*)d_in[3];
    const float* Whh_r  = (const float*)d_in[4];
    const float* bih_r  = (const float*)d_in[5];
    const float* bhh_r  = (const float*)d_in[6];
    const float* Wout   = (const float*)d_in[7];
    const float* bout   = (const float*)d_in[8];
    float* out = (float*)d_out;

    cudaFuncSetAttribute(gemm_gru, cudaFuncAttributeMaxDynamicSharedMemorySize, SMEM_GRU);
    cudaFuncSetAttribute(gemm_out, cudaFuncAttributeMaxDynamicSharedMemorySize, SMEM_OUT);

    float *h0, *h1, *ghl, *ghr;
    cudaGetSymbolAddress((void**)&h0,  g_h0);
    cudaGetSymbolAddress((void**)&h1,  g_h1);
    cudaGetSymbolAddress((void**)&ghl, g_ghl);
    cudaGetSymbolAddress((void**)&ghr, g_ghr);
    float* bufs[2] = { h0, h1 };

    copy_row<<<4, 256>>>(hidden, h0);

    for (int l = 0; l < DEPTH; ++l) {
        int M = 1 << l;
        float* hin  = bufs[l & 1];
        float* hout = bufs[(l + 1) & 1];
        int mt = (M + 127) / 128;
        int S = (l < 8) ? 8 : 4;                  // K-split count
        int kchunk = HDIM / S;
        int pstride = mt * 128 * 3 * HDIM;        // partial-buffer stride
        dim3 grid(mt, 48, S);                     // 24 N-tiles x {L,R} x splits
        gemm_gru<<<grid, 256, SMEM_GRU>>>(hin, Whh_l, Whh_r, ghl, ghr, kchunk, pstride);
        gru_gate<<<M * (HDIM / 256), 256>>>(hin, ghl, ghr,
                                            bih_l, bhh_l, bih_r, bhh_r,
                                            hout, M, S, pstride);
    }

    dim3 gout(1024 / 128, VOCAB / 256);           // (8, 125); x-fast -> Wout L2 reuse
    gemm_out<<<gout, 256, SMEM_OUT>>>(bufs[DEPTH & 1], Wout, out);

    logsoftmax_bias<<<1024, 256>>>(out, bout);
}